// round 8
// baseline (speedup 1.0000x reference)
#include <cuda_runtime.h>
#include <cuda_fp16.h>

#define NN   100000
#define NE   1200000
#define NB   64
#define HID  64
#define IND  128
#define OUTD 2
#define EPSV 1e-5f

// ---------------- scratch (static device globals; no allocation) ----------------
__device__ int   g_degi[NN];
__device__ float g_dinv[NN];
__device__ int   g_bsum[391];
__device__ int   g_rowptr[NN + 1];
__device__ int   g_cur[NN];
__device__ float2 g_edge[NE];          // {coef, src-as-float-bits}; slot-padded reads give coef 0
__device__ uint4  g_hwh4[NN * 8];      // h @ W as fp16x8 per uint4 (64 ch/node)
__device__ float2 g_hw2[NN];           // output-layer hW [N,2] fp32
__device__ float4 g_agg4[NN * 16];     // z buffer (post bias+relu), fp32
__device__ float4 g_h4[NN * 16];       // residual activations, fp32
__device__ float g_stats[3][2 * HID];  // per-layer {sum, sumsq}
__device__ float g_pool[NB * OUTD];
__device__ float g_cnt[NB];

// ---------------- prep ----------------
__global__ void zero_k() {
    int i = blockIdx.x * 256 + threadIdx.x;
    if (i < NN) g_degi[i] = 0;
    if (i < 3 * 2 * HID) ((float*)g_stats)[i] = 0.f;
    if (i < NB * OUTD) g_pool[i] = 0.f;
    if (i < NB) g_cnt[i] = 0.f;
    if (i == 0) g_rowptr[NN] = NE;
}

__global__ void count_k(const int* __restrict__ ei, const int* __restrict__ bat) {
    int e = blockIdx.x * 256 + threadIdx.x;
    if (e < NE) atomicAdd(&g_degi[ei[NE + e]], 1);
    if (e < NN) atomicAdd(&g_cnt[bat[e]], 1.f);
}

__global__ void scan1_k() {
    __shared__ int sh[256];
    int i = blockIdx.x * 256 + threadIdx.x;
    int d = (i < NN) ? g_degi[i] : 0;
    if (i < NN) g_dinv[i] = rsqrtf((float)d + 1.f);
    sh[threadIdx.x] = d;
    __syncthreads();
    for (int off = 128; off; off >>= 1) {
        if (threadIdx.x < off) sh[threadIdx.x] += sh[threadIdx.x + off];
        __syncthreads();
    }
    if (threadIdx.x == 0) g_bsum[blockIdx.x] = sh[0];
}

// merged block-prefix + local scan
__global__ void scan23_k() {
    __shared__ int sh[256];
    __shared__ int base_sh;
    int b = blockIdx.x, t = threadIdx.x;
    int part = 0;
    for (int i = t; i < b; i += 256) part += g_bsum[i];
    sh[t] = part;
    __syncthreads();
    for (int off = 128; off; off >>= 1) {
        if (t < off) sh[t] += sh[t + off];
        __syncthreads();
    }
    if (t == 0) base_sh = sh[0];
    __syncthreads();
    int base = base_sh;
    __syncthreads();
    int i = b * 256 + t;
    int v = (i < NN) ? g_degi[i] : 0;
    sh[t] = v;
    __syncthreads();
    for (int off = 1; off < 256; off <<= 1) {
        int a = (t >= off) ? sh[t - off] : 0;
        __syncthreads();
        sh[t] += a;
        __syncthreads();
    }
    if (i < NN) {
        int rp = base + sh[t] - v;
        g_rowptr[i] = rp;
        g_cur[i] = rp;
    }
}

__global__ void scatter_k(const int* __restrict__ ei) {
    int e = blockIdx.x * 256 + threadIdx.x;
    if (e < NE) {
        int s = ei[e], d = ei[NE + e];
        int pos = atomicAdd(&g_cur[d], 1);
        g_edge[pos] = make_float2(g_dinv[s] * g_dinv[d], __int_as_float(s));
    }
}

// ---------------- HMMA GEMM: hwh[nrows,64](fp16) = Xform(X)[nrows,K] @ W[K,64] ----
// MODE 0: plain; MODE 1: h = X*sc+sh -> g_h4; MODE 2: h = X*sc+sh + g_h4 -> g_h4
#define XPAD 72
template <int K, int MODE>
__global__ void __launch_bounds__(256) gemm_hmma(const float* __restrict__ X,
                                                 const float* __restrict__ W,
                                                 const float* __restrict__ gamma,
                                                 const float* __restrict__ beta,
                                                 const float* __restrict__ st,
                                                 int nrows) {
    __shared__ __half Xs[128][XPAD];
    __shared__ __half Ws[64][XPAD];
    __shared__ float ssc[64], ssh[64];
    const int tid = threadIdx.x;
    if (MODE > 0) {
        if (tid < 64) {
            float s = st[tid], q = st[64 + tid];
            float m = s * (1.f / NN);
            float v = q * (1.f / NN) - m * m;
            float istd = rsqrtf(v + EPSV);
            float sc = istd * gamma[tid];
            ssc[tid] = sc;
            ssh[tid] = beta[tid] - m * sc;
        }
        __syncthreads();
    }
    const int row0 = blockIdx.x * 128;
    const int warp = tid >> 5, lane = tid & 31;
    float acc[8][4] = {};
    float* hh = (float*)g_h4;

    for (int kc = 0; kc < K; kc += 64) {
        {
            int row = tid >> 1;
            int k0 = (tid & 1) * 32;
            int gr = row0 + row;
            #pragma unroll
            for (int i = 0; i < 8; ++i) {
                float4 v = make_float4(0.f, 0.f, 0.f, 0.f);
                if (gr < nrows) {
                    int c = kc + k0 + i * 4;
                    v = *(const float4*)(X + (size_t)gr * K + c);
                    if (MODE > 0) {
                        v.x = v.x * ssc[c + 0] + ssh[c + 0];
                        v.y = v.y * ssc[c + 1] + ssh[c + 1];
                        v.z = v.z * ssc[c + 2] + ssh[c + 2];
                        v.w = v.w * ssc[c + 3] + ssh[c + 3];
                        if (MODE == 2) {
                            float4 o = *(const float4*)(hh + (size_t)gr * 64 + c);
                            v.x += o.x; v.y += o.y; v.z += o.z; v.w += o.w;
                        }
                        *(float4*)(hh + (size_t)gr * 64 + c) = v;
                    }
                }
                *(__half2*)&Xs[row][k0 + i * 4]     = __floats2half2_rn(v.x, v.y);
                *(__half2*)&Xs[row][k0 + i * 4 + 2] = __floats2half2_rn(v.z, v.w);
            }
        }
        {
            int r = tid >> 2;
            int c0 = (tid & 3) * 16;
            #pragma unroll
            for (int i = 0; i < 4; ++i) {
                float4 v = *(const float4*)(W + (size_t)(kc + r) * 64 + c0 + i * 4);
                *(__half2*)&Ws[r][c0 + i * 4]     = __floats2half2_rn(v.x, v.y);
                *(__half2*)&Ws[r][c0 + i * 4 + 2] = __floats2half2_rn(v.z, v.w);
            }
        }
        __syncthreads();

        int r0 = warp * 16;
        #pragma unroll
        for (int k16 = 0; k16 < 64; k16 += 16) {
            unsigned a0, a1, a2, a3;
            {
                const __half* pa = &Xs[r0 + (lane & 15)][k16 + (lane >> 4) * 8];
                unsigned addr = (unsigned)__cvta_generic_to_shared(pa);
                asm volatile("ldmatrix.sync.aligned.m8n8.x4.shared.b16 {%0,%1,%2,%3},[%4];"
                             : "=r"(a0), "=r"(a1), "=r"(a2), "=r"(a3) : "r"(addr));
            }
            #pragma unroll
            for (int nb = 0; nb < 4; ++nb) {
                int c = nb * 16;
                unsigned b0, b1, b2, b3;
                const __half* pb = &Ws[k16 + (lane & 15)][c + (lane >> 4) * 8];
                unsigned addr = (unsigned)__cvta_generic_to_shared(pb);
                asm volatile("ldmatrix.sync.aligned.m8n8.x4.trans.shared.b16 {%0,%1,%2,%3},[%4];"
                             : "=r"(b0), "=r"(b1), "=r"(b2), "=r"(b3) : "r"(addr));
                asm volatile("mma.sync.aligned.m16n8k16.row.col.f32.f16.f16.f32 "
                             "{%0,%1,%2,%3},{%4,%5,%6,%7},{%8,%9},{%0,%1,%2,%3};"
                             : "+f"(acc[2 * nb][0]), "+f"(acc[2 * nb][1]),
                               "+f"(acc[2 * nb][2]), "+f"(acc[2 * nb][3])
                             : "r"(a0), "r"(a1), "r"(a2), "r"(a3), "r"(b0), "r"(b1));
                asm volatile("mma.sync.aligned.m16n8k16.row.col.f32.f16.f16.f32 "
                             "{%0,%1,%2,%3},{%4,%5,%6,%7},{%8,%9},{%0,%1,%2,%3};"
                             : "+f"(acc[2 * nb + 1][0]), "+f"(acc[2 * nb + 1][1]),
                               "+f"(acc[2 * nb + 1][2]), "+f"(acc[2 * nb + 1][3])
                             : "r"(a0), "r"(a1), "r"(a2), "r"(a3), "r"(b2), "r"(b3));
            }
        }
        __syncthreads();
    }

    unsigned* outp = (unsigned*)g_hwh4;
    int gr0 = row0 + warp * 16 + (lane >> 2);
    #pragma unroll
    for (int nb = 0; nb < 8; ++nb) {
        __half2 lo = __floats2half2_rn(acc[nb][0], acc[nb][1]);
        __half2 hi = __floats2half2_rn(acc[nb][2], acc[nb][3]);
        int ci = nb * 4 + (lane & 3);
        if (gr0 < nrows)     outp[(size_t)gr0 * 32 + ci]       = *(unsigned*)&lo;
        if (gr0 + 8 < nrows) outp[(size_t)(gr0 + 8) * 32 + ci] = *(unsigned*)&hi;
    }
}

// ---------------- warp-per-node CSR aggregation + bias + relu + BN stats ----------------
__device__ __forceinline__ void h8acc(uint4 raw, float c, float4& lo, float4& hi) {
    __half2 a = *(__half2*)&raw.x;
    __half2 b = *(__half2*)&raw.y;
    __half2 d = *(__half2*)&raw.z;
    __half2 e = *(__half2*)&raw.w;
    float2 f0 = __half22float2(a), f1 = __half22float2(b);
    float2 f2 = __half22float2(d), f3 = __half22float2(e);
    lo.x += c * f0.x; lo.y += c * f0.y; lo.z += c * f1.x; lo.w += c * f1.y;
    hi.x += c * f2.x; hi.y += c * f2.y; hi.z += c * f3.x; hi.w += c * f3.y;
}

// grid 3125 x 256: 8 warps/block, each warp handles 4 nodes (grid-stride 25000)
__global__ void __launch_bounds__(256) csr_agg_k(const float* __restrict__ bias,
                                                 float* __restrict__ stats) {
    __shared__ float ss[64], qq[64];
    int t = threadIdx.x;
    if (t < 64) { ss[t] = 0.f; qq[t] = 0.f; }
    __syncthreads();
    const int warp = t >> 5, lane = t & 31;
    const int c = lane & 7;         // channel-lane: 8 fp16 channels
    const int eslot = lane >> 3;    // edge group 0..3
    float sacc[8] = {}, qacc[8] = {};
    float4 myb_lo, myb_hi;
    if (lane < 8) {
        myb_lo = ((const float4*)bias)[2 * lane];
        myb_hi = ((const float4*)bias)[2 * lane + 1];
    }

    for (int node = blockIdx.x * 8 + warp; node < NN; node += 25000) {
        int rs = g_rowptr[node], re = g_rowptr[node + 1];
        float4 lo = make_float4(0.f, 0.f, 0.f, 0.f), hi = lo;

        for (int base = rs; base < re; base += 32) {
            int j = base + lane;
            float2 rec = (j < re) ? g_edge[j] : make_float2(0.f, __int_as_float(0));
            int cnt = min(re - base, 32);
            // software-pipelined: one gather in flight
            float cf = __shfl_sync(0xffffffffu, rec.x, eslot);
            int   sv = __shfl_sync(0xffffffffu, __float_as_int(rec.y), eslot);
            uint4 v = g_hwh4[sv * 8 + c];
            for (int k = 4; k < cnt; k += 4) {
                float cf1 = __shfl_sync(0xffffffffu, rec.x, k + eslot);
                int   sv1 = __shfl_sync(0xffffffffu, __float_as_int(rec.y), k + eslot);
                uint4 v1 = g_hwh4[sv1 * 8 + c];
                h8acc(v, cf, lo, hi);
                v = v1; cf = cf1;
            }
            h8acc(v, cf, lo, hi);
        }

        // reduce 4 edge groups -> eslot 0 (lanes 0-7)
        #pragma unroll
        for (int step = 16; step >= 8; step >>= 1) {
            lo.x += __shfl_down_sync(0xffffffffu, lo.x, step);
            lo.y += __shfl_down_sync(0xffffffffu, lo.y, step);
            lo.z += __shfl_down_sync(0xffffffffu, lo.z, step);
            lo.w += __shfl_down_sync(0xffffffffu, lo.w, step);
            hi.x += __shfl_down_sync(0xffffffffu, hi.x, step);
            hi.y += __shfl_down_sync(0xffffffffu, hi.y, step);
            hi.z += __shfl_down_sync(0xffffffffu, hi.z, step);
            hi.w += __shfl_down_sync(0xffffffffu, hi.w, step);
        }

        if (lane < 8) {
            float d = g_dinv[node];
            h8acc(g_hwh4[node * 8 + lane], d * d, lo, hi);   // self-loop
            lo.x = fmaxf(lo.x + myb_lo.x, 0.f); lo.y = fmaxf(lo.y + myb_lo.y, 0.f);
            lo.z = fmaxf(lo.z + myb_lo.z, 0.f); lo.w = fmaxf(lo.w + myb_lo.w, 0.f);
            hi.x = fmaxf(hi.x + myb_hi.x, 0.f); hi.y = fmaxf(hi.y + myb_hi.y, 0.f);
            hi.z = fmaxf(hi.z + myb_hi.z, 0.f); hi.w = fmaxf(hi.w + myb_hi.w, 0.f);
            g_agg4[node * 16 + 2 * lane]     = lo;
            g_agg4[node * 16 + 2 * lane + 1] = hi;
            float zz[8] = {lo.x, lo.y, lo.z, lo.w, hi.x, hi.y, hi.z, hi.w};
            #pragma unroll
            for (int k = 0; k < 8; ++k) {
                sacc[k] += zz[k];
                qacc[k] += zz[k] * zz[k];
            }
        }
    }

    if (lane < 8) {
        #pragma unroll
        for (int k = 0; k < 8; ++k) {
            atomicAdd(&ss[8 * lane + k], sacc[k]);
            atomicAdd(&qq[8 * lane + k], qacc[k]);
        }
    }
    __syncthreads();
    if (t < 64) {
        atomicAdd(&stats[t], ss[t]);
        atomicAdd(&stats[64 + t], qq[t]);
    }
}

// ---------------- output layer: fused BN+residual, 64 -> 2, thread-per-row ----------------
__global__ void __launch_bounds__(256) gemm_out_k(const float* __restrict__ Z,
                                                  const float* __restrict__ W,
                                                  const float* __restrict__ gamma,
                                                  const float* __restrict__ beta,
                                                  const float* __restrict__ st) {
    __shared__ float w0[64], w1[64], ssc[64], ssh[64];
    if (threadIdx.x < 64) {
        int c = threadIdx.x;
        w0[c] = W[c * 2];
        w1[c] = W[c * 2 + 1];
        float s = st[c], q = st[64 + c];
        float m = s * (1.f / NN);
        float v = q * (1.f / NN) - m * m;
        float istd = rsqrtf(v + EPSV);
        float sc = istd * gamma[c];
        ssc[c] = sc;
        ssh[c] = beta[c] - m * sc;
    }
    __syncthreads();
    int row = blockIdx.x * 256 + threadIdx.x;
    if (row >= NN) return;
    const float4* zr = (const float4*)(Z + (size_t)row * 64);
    const float4* hr = (const float4*)((const float*)g_h4 + (size_t)row * 64);
    float a0 = 0.f, a1 = 0.f;
    #pragma unroll
    for (int k4 = 0; k4 < 16; ++k4) {
        float4 z = zr[k4];
        float4 o = hr[k4];
        int c = k4 * 4;
        float h0 = z.x * ssc[c + 0] + ssh[c + 0] + o.x;
        float h1 = z.y * ssc[c + 1] + ssh[c + 1] + o.y;
        float h2 = z.z * ssc[c + 2] + ssh[c + 2] + o.z;
        float h3 = z.w * ssc[c + 3] + ssh[c + 3] + o.w;
        a0 += h0 * w0[c + 0] + h1 * w0[c + 1] + h2 * w0[c + 2] + h3 * w0[c + 3];
        a1 += h0 * w1[c + 0] + h1 * w1[c + 1] + h2 * w1[c + 2] + h3 * w1[c + 3];
    }
    g_hw2[row] = make_float2(a0, a1);
}

// fused: CSR aggregation (2 channels) + segment pooling
__global__ void __launch_bounds__(256) csr2_pool_k(const int* __restrict__ bat) {
    __shared__ float sp[NB * OUTD];
    int t = threadIdx.x;
    if (t < NB * OUTD) sp[t] = 0.f;
    __syncthreads();
    int i = blockIdx.x * 256 + t;
    if (i < NN) {
        float d = g_dinv[i];
        float dd = d * d;
        float2 a = g_hw2[i];
        a.x *= dd; a.y *= dd;
        int rs = g_rowptr[i], re = g_rowptr[i + 1];
        int j = rs;
        for (; j + 4 <= re; j += 4) {
            float2 e0 = g_edge[j], e1 = g_edge[j + 1], e2 = g_edge[j + 2], e3 = g_edge[j + 3];
            float2 v0 = g_hw2[__float_as_int(e0.y)];
            float2 v1 = g_hw2[__float_as_int(e1.y)];
            float2 v2 = g_hw2[__float_as_int(e2.y)];
            float2 v3 = g_hw2[__float_as_int(e3.y)];
            a.x += e0.x * v0.x + e1.x * v1.x + e2.x * v2.x + e3.x * v3.x;
            a.y += e0.x * v0.y + e1.x * v1.y + e2.x * v2.y + e3.x * v3.y;
        }
        for (; j < re; ++j) {
            float2 e = g_edge[j];
            float2 v = g_hw2[__float_as_int(e.y)];
            a.x += e.x * v.x; a.y += e.x * v.y;
        }
        int b = bat[i];
        atomicAdd(&sp[2 * b],     a.x);
        atomicAdd(&sp[2 * b + 1], a.y);
    }
    __syncthreads();
    if (t < NB * OUTD) atomicAdd(&g_pool[t], sp[t]);
}

__global__ void final_k(const float* __restrict__ b_out, float* __restrict__ out) {
    int t = threadIdx.x;
    if (t < NB * OUTD) {
        int b = t >> 1, c = t & 1;
        out[t] = g_pool[t] / fmaxf(g_cnt[b], 1.f) + b_out[c];
    }
}

// ---------------- driver ----------------
extern "C" void kernel_launch(void* const* d_in, const int* in_sizes, int n_in,
                              void* d_out, int out_size) {
    const float* x       = (const float*)d_in[0];
    const float* W_in    = (const float*)d_in[1];
    const float* b_in    = (const float*)d_in[2];
    const float* W_h     = (const float*)d_in[3];
    const float* b_h     = (const float*)d_in[4];
    const float* W_out   = (const float*)d_in[5];
    const float* b_out   = (const float*)d_in[6];
    const float* bn_g    = (const float*)d_in[7];
    const float* bn_b    = (const float*)d_in[8];
    const int*   ei      = (const int*)d_in[9];
    const int*   bat     = (const int*)d_in[10];

    float* out = (float*)d_out;

    void *p_z, *p_st;
    cudaGetSymbolAddress(&p_z, g_agg4);
    cudaGetSymbolAddress(&p_st, g_stats);
    float* z  = (float*)p_z;
    float* st = (float*)p_st;   // 3 layers x 128

    // prep (5 launches)
    zero_k<<<391, 256>>>();
    count_k<<<4688, 256>>>(ei, bat);
    scan1_k<<<391, 256>>>();
    scan23_k<<<391, 256>>>();
    scatter_k<<<4688, 256>>>(ei);

    // layer 1: 128 -> 64
    gemm_hmma<IND, 0><<<782, 256>>>(x, W_in, nullptr, nullptr, nullptr, NN);
    csr_agg_k<<<3125, 256>>>(b_in, st);

    // layer 2
    gemm_hmma<HID, 1><<<782, 256>>>(z, W_h, bn_g, bn_b, st, NN);
    csr_agg_k<<<3125, 256>>>(b_h, st + 128);

    // layer 3
    gemm_hmma<HID, 2><<<782, 256>>>(z, W_h + HID * HID, bn_g + HID, bn_b + HID, st + 128, NN);
    csr_agg_k<<<3125, 256>>>(b_h + HID, st + 256);

    // output layer
    gemm_out_k<<<391, 256>>>(z, W_out, bn_g + 2 * HID, bn_b + 2 * HID, st + 256);
    csr2_pool_k<<<391, 256>>>(bat);
    final_k<<<1, 128>>>(b_out, out);
}

// round 9
// speedup vs baseline: 1.1637x; 1.1637x over previous
#include <cuda_runtime.h>
#include <cuda_fp16.h>

#define NN   100000
#define NE   1200000
#define NB   64
#define HID  64
#define IND  128
#define OUTD 2
#define EPSV 1e-5f

// ---------------- scratch (static device globals; no allocation) ----------------
__device__ int   g_degi[NN];
__device__ float g_dinv[NN];
__device__ int   g_bsum[391];
__device__ int   g_rowptr[NN + 1];
__device__ int   g_cur[NN];
__device__ float2 g_edge[NE];          // {coef, src-as-float-bits}
__device__ uint4  g_hwh4[NN * 8];      // h @ W as fp16x8 per uint4 (64 ch/node)
__device__ float2 g_hw2[NN];           // output-layer hW [N,2] fp32
__device__ float4 g_agg4[NN * 16];     // z buffer (post bias+relu), fp32
__device__ float4 g_h4[NN * 16];       // residual activations, fp32
__device__ float g_stats[3][2 * HID];  // per-layer {sum, sumsq}
__device__ float g_pool[NB * OUTD];
__device__ float g_cnt[NB];

// ---------------- prep ----------------
__global__ void zero_k() {
    int i = blockIdx.x * 256 + threadIdx.x;
    if (i < NN) g_degi[i] = 0;
    if (i < 3 * 2 * HID) ((float*)g_stats)[i] = 0.f;
    if (i < NB * OUTD) g_pool[i] = 0.f;
    if (i < NB) g_cnt[i] = 0.f;
    if (i == 0) g_rowptr[NN] = NE;
}

__global__ void count_k(const int* __restrict__ ei, const int* __restrict__ bat) {
    int e = blockIdx.x * 256 + threadIdx.x;
    if (e < NE) atomicAdd(&g_degi[ei[NE + e]], 1);
    if (e < NN) atomicAdd(&g_cnt[bat[e]], 1.f);
}

__global__ void scan1_k() {
    __shared__ int sh[256];
    int i = blockIdx.x * 256 + threadIdx.x;
    int d = (i < NN) ? g_degi[i] : 0;
    if (i < NN) g_dinv[i] = rsqrtf((float)d + 1.f);
    sh[threadIdx.x] = d;
    __syncthreads();
    for (int off = 128; off; off >>= 1) {
        if (threadIdx.x < off) sh[threadIdx.x] += sh[threadIdx.x + off];
        __syncthreads();
    }
    if (threadIdx.x == 0) g_bsum[blockIdx.x] = sh[0];
}

// merged block-prefix + local scan
__global__ void scan23_k() {
    __shared__ int sh[256];
    __shared__ int base_sh;
    int b = blockIdx.x, t = threadIdx.x;
    int part = 0;
    for (int i = t; i < b; i += 256) part += g_bsum[i];
    sh[t] = part;
    __syncthreads();
    for (int off = 128; off; off >>= 1) {
        if (t < off) sh[t] += sh[t + off];
        __syncthreads();
    }
    if (t == 0) base_sh = sh[0];
    __syncthreads();
    int base = base_sh;
    __syncthreads();
    int i = b * 256 + t;
    int v = (i < NN) ? g_degi[i] : 0;
    sh[t] = v;
    __syncthreads();
    for (int off = 1; off < 256; off <<= 1) {
        int a = (t >= off) ? sh[t - off] : 0;
        __syncthreads();
        sh[t] += a;
        __syncthreads();
    }
    if (i < NN) {
        int rp = base + sh[t] - v;
        g_rowptr[i] = rp;
        g_cur[i] = rp;
    }
}

__global__ void scatter_k(const int* __restrict__ ei) {
    int e = blockIdx.x * 256 + threadIdx.x;
    if (e < NE) {
        int s = ei[e], d = ei[NE + e];
        int pos = atomicAdd(&g_cur[d], 1);
        g_edge[pos] = make_float2(g_dinv[s] * g_dinv[d], __int_as_float(s));
    }
}

// ---------------- HMMA GEMM: hwh[nrows,64](fp16) = Xform(X)[nrows,K] @ W[K,64] ----
// MODE 0: plain; MODE 1: h = X*sc+sh -> g_h4; MODE 2: h = X*sc+sh + g_h4 -> g_h4
#define XPAD 72
template <int K, int MODE>
__global__ void __launch_bounds__(256) gemm_hmma(const float* __restrict__ X,
                                                 const float* __restrict__ W,
                                                 const float* __restrict__ gamma,
                                                 const float* __restrict__ beta,
                                                 const float* __restrict__ st,
                                                 int nrows) {
    __shared__ __half Xs[128][XPAD];
    __shared__ __half Ws[64][XPAD];
    __shared__ float ssc[64], ssh[64];
    const int tid = threadIdx.x;
    if (MODE > 0) {
        if (tid < 64) {
            float s = st[tid], q = st[64 + tid];
            float m = s * (1.f / NN);
            float v = q * (1.f / NN) - m * m;
            float istd = rsqrtf(v + EPSV);
            float sc = istd * gamma[tid];
            ssc[tid] = sc;
            ssh[tid] = beta[tid] - m * sc;
        }
        __syncthreads();
    }
    const int row0 = blockIdx.x * 128;
    const int warp = tid >> 5, lane = tid & 31;
    float acc[8][4] = {};
    float* hh = (float*)g_h4;

    for (int kc = 0; kc < K; kc += 64) {
        {
            int row = tid >> 1;
            int k0 = (tid & 1) * 32;
            int gr = row0 + row;
            #pragma unroll
            for (int i = 0; i < 8; ++i) {
                float4 v = make_float4(0.f, 0.f, 0.f, 0.f);
                if (gr < nrows) {
                    int c = kc + k0 + i * 4;
                    v = *(const float4*)(X + (size_t)gr * K + c);
                    if (MODE > 0) {
                        v.x = v.x * ssc[c + 0] + ssh[c + 0];
                        v.y = v.y * ssc[c + 1] + ssh[c + 1];
                        v.z = v.z * ssc[c + 2] + ssh[c + 2];
                        v.w = v.w * ssc[c + 3] + ssh[c + 3];
                        if (MODE == 2) {
                            float4 o = *(const float4*)(hh + (size_t)gr * 64 + c);
                            v.x += o.x; v.y += o.y; v.z += o.z; v.w += o.w;
                        }
                        *(float4*)(hh + (size_t)gr * 64 + c) = v;
                    }
                }
                *(__half2*)&Xs[row][k0 + i * 4]     = __floats2half2_rn(v.x, v.y);
                *(__half2*)&Xs[row][k0 + i * 4 + 2] = __floats2half2_rn(v.z, v.w);
            }
        }
        {
            int r = tid >> 2;
            int c0 = (tid & 3) * 16;
            #pragma unroll
            for (int i = 0; i < 4; ++i) {
                float4 v = *(const float4*)(W + (size_t)(kc + r) * 64 + c0 + i * 4);
                *(__half2*)&Ws[r][c0 + i * 4]     = __floats2half2_rn(v.x, v.y);
                *(__half2*)&Ws[r][c0 + i * 4 + 2] = __floats2half2_rn(v.z, v.w);
            }
        }
        __syncthreads();

        int r0 = warp * 16;
        #pragma unroll
        for (int k16 = 0; k16 < 64; k16 += 16) {
            unsigned a0, a1, a2, a3;
            {
                const __half* pa = &Xs[r0 + (lane & 15)][k16 + (lane >> 4) * 8];
                unsigned addr = (unsigned)__cvta_generic_to_shared(pa);
                asm volatile("ldmatrix.sync.aligned.m8n8.x4.shared.b16 {%0,%1,%2,%3},[%4];"
                             : "=r"(a0), "=r"(a1), "=r"(a2), "=r"(a3) : "r"(addr));
            }
            #pragma unroll
            for (int nb = 0; nb < 4; ++nb) {
                int c = nb * 16;
                unsigned b0, b1, b2, b3;
                const __half* pb = &Ws[k16 + (lane & 15)][c + (lane >> 4) * 8];
                unsigned addr = (unsigned)__cvta_generic_to_shared(pb);
                asm volatile("ldmatrix.sync.aligned.m8n8.x4.trans.shared.b16 {%0,%1,%2,%3},[%4];"
                             : "=r"(b0), "=r"(b1), "=r"(b2), "=r"(b3) : "r"(addr));
                asm volatile("mma.sync.aligned.m16n8k16.row.col.f32.f16.f16.f32 "
                             "{%0,%1,%2,%3},{%4,%5,%6,%7},{%8,%9},{%0,%1,%2,%3};"
                             : "+f"(acc[2 * nb][0]), "+f"(acc[2 * nb][1]),
                               "+f"(acc[2 * nb][2]), "+f"(acc[2 * nb][3])
                             : "r"(a0), "r"(a1), "r"(a2), "r"(a3), "r"(b0), "r"(b1));
                asm volatile("mma.sync.aligned.m16n8k16.row.col.f32.f16.f16.f32 "
                             "{%0,%1,%2,%3},{%4,%5,%6,%7},{%8,%9},{%0,%1,%2,%3};"
                             : "+f"(acc[2 * nb + 1][0]), "+f"(acc[2 * nb + 1][1]),
                               "+f"(acc[2 * nb + 1][2]), "+f"(acc[2 * nb + 1][3])
                             : "r"(a0), "r"(a1), "r"(a2), "r"(a3), "r"(b2), "r"(b3));
            }
        }
        __syncthreads();
    }

    unsigned* outp = (unsigned*)g_hwh4;
    int gr0 = row0 + warp * 16 + (lane >> 2);
    #pragma unroll
    for (int nb = 0; nb < 8; ++nb) {
        __half2 lo = __floats2half2_rn(acc[nb][0], acc[nb][1]);
        __half2 hi = __floats2half2_rn(acc[nb][2], acc[nb][3]);
        int ci = nb * 4 + (lane & 3);
        if (gr0 < nrows)     outp[(size_t)gr0 * 32 + ci]       = *(unsigned*)&lo;
        if (gr0 + 8 < nrows) outp[(size_t)(gr0 + 8) * 32 + ci] = *(unsigned*)&hi;
    }
}

// ---------------- fused CSR aggregation + bias + relu + BN stats (R7 layout) ----------------
__device__ __forceinline__ void h8acc(uint4 raw, float c, float4& lo, float4& hi) {
    __half2 a = *(__half2*)&raw.x;
    __half2 b = *(__half2*)&raw.y;
    __half2 d = *(__half2*)&raw.z;
    __half2 e = *(__half2*)&raw.w;
    float2 f0 = __half22float2(a), f1 = __half22float2(b);
    float2 f2 = __half22float2(d), f3 = __half22float2(e);
    lo.x += c * f0.x; lo.y += c * f0.y; lo.z += c * f1.x; lo.w += c * f1.y;
    hi.x += c * f2.x; hi.y += c * f2.y; hi.z += c * f3.x; hi.w += c * f3.y;
}
__device__ __forceinline__ void h8scale(uint4 raw, float c, float4& lo, float4& hi) {
    __half2 a = *(__half2*)&raw.x;
    __half2 b = *(__half2*)&raw.y;
    __half2 d = *(__half2*)&raw.z;
    __half2 e = *(__half2*)&raw.w;
    float2 f0 = __half22float2(a), f1 = __half22float2(b);
    float2 f2 = __half22float2(d), f3 = __half22float2(e);
    lo = make_float4(c * f0.x, c * f0.y, c * f1.x, c * f1.y);
    hi = make_float4(c * f2.x, c * f2.y, c * f3.x, c * f3.y);
}

__global__ void __launch_bounds__(256) csr_agg_k(const float* __restrict__ bias,
                                                 float* __restrict__ stats) {
    __shared__ float ss[64], qq[64];
    int t = threadIdx.x;
    if (t < 64) { ss[t] = 0.f; qq[t] = 0.f; }
    __syncthreads();

    int idx = blockIdx.x * 256 + t;            // exactly NN*8
    int node = idx >> 3, q = idx & 7;
    int rs = g_rowptr[node], re = g_rowptr[node + 1];
    float d = g_dinv[node];
    float dd = d * d;
    float4 lo, hi;
    h8scale(g_hwh4[idx], dd, lo, hi);

    int j = rs;
    for (; j + 8 <= re; j += 8) {              // 8-way MLP
        float2 er[8];
        uint4  vr[8];
        #pragma unroll
        for (int k = 0; k < 8; ++k) er[k] = g_edge[j + k];
        #pragma unroll
        for (int k = 0; k < 8; ++k) vr[k] = g_hwh4[__float_as_int(er[k].y) * 8 + q];
        #pragma unroll
        for (int k = 0; k < 8; ++k) h8acc(vr[k], er[k].x, lo, hi);
    }
    for (; j + 4 <= re; j += 4) {              // 4-way tail
        float2 e0 = g_edge[j], e1 = g_edge[j + 1], e2 = g_edge[j + 2], e3 = g_edge[j + 3];
        uint4 v0 = g_hwh4[__float_as_int(e0.y) * 8 + q];
        uint4 v1 = g_hwh4[__float_as_int(e1.y) * 8 + q];
        uint4 v2 = g_hwh4[__float_as_int(e2.y) * 8 + q];
        uint4 v3 = g_hwh4[__float_as_int(e3.y) * 8 + q];
        h8acc(v0, e0.x, lo, hi);
        h8acc(v1, e1.x, lo, hi);
        h8acc(v2, e2.x, lo, hi);
        h8acc(v3, e3.x, lo, hi);
    }
    for (; j < re; ++j) {
        float2 e = g_edge[j];
        h8acc(g_hwh4[__float_as_int(e.y) * 8 + q], e.x, lo, hi);
    }

    float4 blo = ((const float4*)bias)[2 * q];
    float4 bhi = ((const float4*)bias)[2 * q + 1];
    lo.x = fmaxf(lo.x + blo.x, 0.f); lo.y = fmaxf(lo.y + blo.y, 0.f);
    lo.z = fmaxf(lo.z + blo.z, 0.f); lo.w = fmaxf(lo.w + blo.w, 0.f);
    hi.x = fmaxf(hi.x + bhi.x, 0.f); hi.y = fmaxf(hi.y + bhi.y, 0.f);
    hi.z = fmaxf(hi.z + bhi.z, 0.f); hi.w = fmaxf(hi.w + bhi.w, 0.f);
    g_agg4[node * 16 + 2 * q]     = lo;
    g_agg4[node * 16 + 2 * q + 1] = hi;

    float s[8] = {lo.x, lo.y, lo.z, lo.w, hi.x, hi.y, hi.z, hi.w};
    float sq[8];
    #pragma unroll
    for (int k = 0; k < 8; ++k) sq[k] = s[k] * s[k];
    #pragma unroll
    for (int k = 0; k < 8; ++k) {
        s[k]  += __shfl_down_sync(0xffffffffu, s[k], 16);
        sq[k] += __shfl_down_sync(0xffffffffu, sq[k], 16);
        s[k]  += __shfl_down_sync(0xffffffffu, s[k], 8);
        sq[k] += __shfl_down_sync(0xffffffffu, sq[k], 8);
    }
    if ((t & 31) < 8) {
        #pragma unroll
        for (int k = 0; k < 8; ++k) {
            atomicAdd(&ss[8 * q + k], s[k]);
            atomicAdd(&qq[8 * q + k], sq[k]);
        }
    }
    __syncthreads();
    if (t < 64) {
        atomicAdd(&stats[t], ss[t]);
        atomicAdd(&stats[64 + t], qq[t]);
    }
}

// ---------------- output layer: fused BN+residual, 64 -> 2, thread-per-row ----------------
__global__ void __launch_bounds__(256) gemm_out_k(const float* __restrict__ Z,
                                                  const float* __restrict__ W,
                                                  const float* __restrict__ gamma,
                                                  const float* __restrict__ beta,
                                                  const float* __restrict__ st) {
    __shared__ float w0[64], w1[64], ssc[64], ssh[64];
    if (threadIdx.x < 64) {
        int c = threadIdx.x;
        w0[c] = W[c * 2];
        w1[c] = W[c * 2 + 1];
        float s = st[c], q = st[64 + c];
        float m = s * (1.f / NN);
        float v = q * (1.f / NN) - m * m;
        float istd = rsqrtf(v + EPSV);
        float sc = istd * gamma[c];
        ssc[c] = sc;
        ssh[c] = beta[c] - m * sc;
    }
    __syncthreads();
    int row = blockIdx.x * 256 + threadIdx.x;
    if (row >= NN) return;
    const float4* zr = (const float4*)(Z + (size_t)row * 64);
    const float4* hr = (const float4*)((const float*)g_h4 + (size_t)row * 64);
    float a0 = 0.f, a1 = 0.f;
    #pragma unroll
    for (int k4 = 0; k4 < 16; ++k4) {
        float4 z = zr[k4];
        float4 o = hr[k4];
        int c = k4 * 4;
        float h0 = z.x * ssc[c + 0] + ssh[c + 0] + o.x;
        float h1 = z.y * ssc[c + 1] + ssh[c + 1] + o.y;
        float h2 = z.z * ssc[c + 2] + ssh[c + 2] + o.z;
        float h3 = z.w * ssc[c + 3] + ssh[c + 3] + o.w;
        a0 += h0 * w0[c + 0] + h1 * w0[c + 1] + h2 * w0[c + 2] + h3 * w0[c + 3];
        a1 += h0 * w1[c + 0] + h1 * w1[c + 1] + h2 * w1[c + 2] + h3 * w1[c + 3];
    }
    g_hw2[row] = make_float2(a0, a1);
}

// fused: CSR aggregation (2 channels) + segment pooling
__global__ void __launch_bounds__(256) csr2_pool_k(const int* __restrict__ bat) {
    __shared__ float sp[NB * OUTD];
    int t = threadIdx.x;
    if (t < NB * OUTD) sp[t] = 0.f;
    __syncthreads();
    int i = blockIdx.x * 256 + t;
    if (i < NN) {
        float d = g_dinv[i];
        float dd = d * d;
        float2 a = g_hw2[i];
        a.x *= dd; a.y *= dd;
        int rs = g_rowptr[i], re = g_rowptr[i + 1];
        int j = rs;
        for (; j + 4 <= re; j += 4) {
            float2 e0 = g_edge[j], e1 = g_edge[j + 1], e2 = g_edge[j + 2], e3 = g_edge[j + 3];
            float2 v0 = g_hw2[__float_as_int(e0.y)];
            float2 v1 = g_hw2[__float_as_int(e1.y)];
            float2 v2 = g_hw2[__float_as_int(e2.y)];
            float2 v3 = g_hw2[__float_as_int(e3.y)];
            a.x += e0.x * v0.x + e1.x * v1.x + e2.x * v2.x + e3.x * v3.x;
            a.y += e0.x * v0.y + e1.x * v1.y + e2.x * v2.y + e3.x * v3.y;
        }
        for (; j < re; ++j) {
            float2 e = g_edge[j];
            float2 v = g_hw2[__float_as_int(e.y)];
            a.x += e.x * v.x; a.y += e.x * v.y;
        }
        int b = bat[i];
        atomicAdd(&sp[2 * b],     a.x);
        atomicAdd(&sp[2 * b + 1], a.y);
    }
    __syncthreads();
    if (t < NB * OUTD) atomicAdd(&g_pool[t], sp[t]);
}

__global__ void final_k(const float* __restrict__ b_out, float* __restrict__ out) {
    int t = threadIdx.x;
    if (t < NB * OUTD) {
        int b = t >> 1, c = t & 1;
        out[t] = g_pool[t] / fmaxf(g_cnt[b], 1.f) + b_out[c];
    }
}

// ---------------- driver ----------------
extern "C" void kernel_launch(void* const* d_in, const int* in_sizes, int n_in,
                              void* d_out, int out_size) {
    const float* x       = (const float*)d_in[0];
    const float* W_in    = (const float*)d_in[1];
    const float* b_in    = (const float*)d_in[2];
    const float* W_h     = (const float*)d_in[3];
    const float* b_h     = (const float*)d_in[4];
    const float* W_out   = (const float*)d_in[5];
    const float* b_out   = (const float*)d_in[6];
    const float* bn_g    = (const float*)d_in[7];
    const float* bn_b    = (const float*)d_in[8];
    const int*   ei      = (const int*)d_in[9];
    const int*   bat     = (const int*)d_in[10];

    float* out = (float*)d_out;

    void *p_z, *p_st;
    cudaGetSymbolAddress(&p_z, g_agg4);
    cudaGetSymbolAddress(&p_st, g_stats);
    float* z  = (float*)p_z;
    float* st = (float*)p_st;   // 3 layers x 128

    // prep (5 launches)
    zero_k<<<391, 256>>>();
    count_k<<<4688, 256>>>(ei, bat);
    scan1_k<<<391, 256>>>();
    scan23_k<<<391, 256>>>();
    scatter_k<<<4688, 256>>>(ei);

    // layer 1: 128 -> 64
    gemm_hmma<IND, 0><<<782, 256>>>(x, W_in, nullptr, nullptr, nullptr, NN);
    csr_agg_k<<<3125, 256>>>(b_in, st);

    // layer 2
    gemm_hmma<HID, 1><<<782, 256>>>(z, W_h, bn_g, bn_b, st, NN);
    csr_agg_k<<<3125, 256>>>(b_h, st + 128);

    // layer 3
    gemm_hmma<HID, 2><<<782, 256>>>(z, W_h + HID * HID, bn_g + HID, bn_b + HID, st + 128, NN);
    csr_agg_k<<<3125, 256>>>(b_h + HID, st + 256);

    // output layer
    gemm_out_k<<<391, 256>>>(z, W_out, bn_g + 2 * HID, bn_b + 2 * HID, st + 256);
    csr2_pool_k<<<391, 256>>>(bat);
    final_k<<<1, 128>>>(b_out, out);
}

// round 10
// speedup vs baseline: 1.2109x; 1.0406x over previous
#include <cuda_runtime.h>
#include <cuda_fp16.h>

#define NN   100000
#define NE   1200000
#define NB   64
#define HID  64
#define IND  128
#define OUTD 2
#define EPSV 1e-5f

// ---------------- scratch (static device globals; no allocation) ----------------
__device__ int   g_degi[NN];
__device__ float g_dinv[NN];
__device__ int   g_bsum[391];
__device__ int   g_rowptr[NN + 1];
__device__ int   g_cur[NN];
__device__ float2 g_edge[NE];          // {coef, src-as-float-bits}
__device__ uint4  g_hwh4[NN * 8];      // h @ W as fp16x8 per uint4 (64 ch/node)
__device__ float2 g_hw2[NN];           // output-layer hW [N,2] fp32
__device__ float4 g_agg4[NN * 16];     // z buffer (post bias+relu), fp32
__device__ float4 g_h4[NN * 16];       // residual activations, fp32
__device__ float g_stats[3][2 * HID];  // per-layer {sum, sumsq}
__device__ float g_pool[NB * OUTD];
__device__ float g_cnt[NB];

// ---------------- prep ----------------
__global__ void zero_k() {
    int i = blockIdx.x * 256 + threadIdx.x;
    if (i < NN) g_degi[i] = 0;
    if (i < 3 * 2 * HID) ((float*)g_stats)[i] = 0.f;
    if (i < NB * OUTD) g_pool[i] = 0.f;
    if (i < NB) g_cnt[i] = 0.f;
    if (i == 0) g_rowptr[NN] = NE;
}

__global__ void count_k(const int* __restrict__ ei, const int* __restrict__ bat) {
    int e = blockIdx.x * 256 + threadIdx.x;
    if (e < NE) atomicAdd(&g_degi[ei[NE + e]], 1);
    if (e < NN) atomicAdd(&g_cnt[bat[e]], 1.f);
}

__global__ void scan1_k() {
    __shared__ int sh[256];
    int i = blockIdx.x * 256 + threadIdx.x;
    int d = (i < NN) ? g_degi[i] : 0;
    if (i < NN) g_dinv[i] = rsqrtf((float)d + 1.f);
    sh[threadIdx.x] = d;
    __syncthreads();
    for (int off = 128; off; off >>= 1) {
        if (threadIdx.x < off) sh[threadIdx.x] += sh[threadIdx.x + off];
        __syncthreads();
    }
    if (threadIdx.x == 0) g_bsum[blockIdx.x] = sh[0];
}

// merged block-prefix + local scan
__global__ void scan23_k() {
    __shared__ int sh[256];
    __shared__ int base_sh;
    int b = blockIdx.x, t = threadIdx.x;
    int part = 0;
    for (int i = t; i < b; i += 256) part += g_bsum[i];
    sh[t] = part;
    __syncthreads();
    for (int off = 128; off; off >>= 1) {
        if (t < off) sh[t] += sh[t + off];
        __syncthreads();
    }
    if (t == 0) base_sh = sh[0];
    __syncthreads();
    int base = base_sh;
    __syncthreads();
    int i = b * 256 + t;
    int v = (i < NN) ? g_degi[i] : 0;
    sh[t] = v;
    __syncthreads();
    for (int off = 1; off < 256; off <<= 1) {
        int a = (t >= off) ? sh[t - off] : 0;
        __syncthreads();
        sh[t] += a;
        __syncthreads();
    }
    if (i < NN) {
        int rp = base + sh[t] - v;
        g_rowptr[i] = rp;
        g_cur[i] = rp;
    }
}

__global__ void scatter_k(const int* __restrict__ ei) {
    int e = blockIdx.x * 256 + threadIdx.x;
    if (e < NE) {
        int s = ei[e], d = ei[NE + e];
        int pos = atomicAdd(&g_cur[d], 1);
        g_edge[pos] = make_float2(g_dinv[s] * g_dinv[d], __int_as_float(s));
    }
}

// ---------------- HMMA GEMM: hwh[nrows,64](fp16) = Xform(X)[nrows,K] @ W[K,64] ----
// MODE 0: plain; MODE 1: h = X*sc+sh -> g_h4; MODE 2: h = X*sc+sh + g_h4 -> g_h4
#define XPAD 72
template <int K, int MODE>
__global__ void __launch_bounds__(256) gemm_hmma(const float* __restrict__ X,
                                                 const float* __restrict__ W,
                                                 const float* __restrict__ gamma,
                                                 const float* __restrict__ beta,
                                                 const float* __restrict__ st,
                                                 int nrows) {
    __shared__ __half Xs[128][XPAD];
    __shared__ __half Ws[64][XPAD];
    __shared__ float ssc[64], ssh[64];
    const int tid = threadIdx.x;
    if (MODE > 0) {
        if (tid < 64) {
            float s = st[tid], q = st[64 + tid];
            float m = s * (1.f / NN);
            float v = q * (1.f / NN) - m * m;
            float istd = rsqrtf(v + EPSV);
            float sc = istd * gamma[tid];
            ssc[tid] = sc;
            ssh[tid] = beta[tid] - m * sc;
        }
        __syncthreads();
    }
    const int row0 = blockIdx.x * 128;
    const int warp = tid >> 5, lane = tid & 31;
    float acc[8][4] = {};
    float* hh = (float*)g_h4;

    for (int kc = 0; kc < K; kc += 64) {
        {
            int row = tid >> 1;
            int k0 = (tid & 1) * 32;
            int gr = row0 + row;
            #pragma unroll
            for (int i = 0; i < 8; ++i) {
                float4 v = make_float4(0.f, 0.f, 0.f, 0.f);
                if (gr < nrows) {
                    int c = kc + k0 + i * 4;
                    v = *(const float4*)(X + (size_t)gr * K + c);
                    if (MODE > 0) {
                        v.x = v.x * ssc[c + 0] + ssh[c + 0];
                        v.y = v.y * ssc[c + 1] + ssh[c + 1];
                        v.z = v.z * ssc[c + 2] + ssh[c + 2];
                        v.w = v.w * ssc[c + 3] + ssh[c + 3];
                        if (MODE == 2) {
                            float4 o = *(const float4*)(hh + (size_t)gr * 64 + c);
                            v.x += o.x; v.y += o.y; v.z += o.z; v.w += o.w;
                        }
                        *(float4*)(hh + (size_t)gr * 64 + c) = v;
                    }
                }
                *(__half2*)&Xs[row][k0 + i * 4]     = __floats2half2_rn(v.x, v.y);
                *(__half2*)&Xs[row][k0 + i * 4 + 2] = __floats2half2_rn(v.z, v.w);
            }
        }
        {
            int r = tid >> 2;
            int c0 = (tid & 3) * 16;
            #pragma unroll
            for (int i = 0; i < 4; ++i) {
                float4 v = *(const float4*)(W + (size_t)(kc + r) * 64 + c0 + i * 4);
                *(__half2*)&Ws[r][c0 + i * 4]     = __floats2half2_rn(v.x, v.y);
                *(__half2*)&Ws[r][c0 + i * 4 + 2] = __floats2half2_rn(v.z, v.w);
            }
        }
        __syncthreads();

        int r0 = warp * 16;
        #pragma unroll
        for (int k16 = 0; k16 < 64; k16 += 16) {
            unsigned a0, a1, a2, a3;
            {
                const __half* pa = &Xs[r0 + (lane & 15)][k16 + (lane >> 4) * 8];
                unsigned addr = (unsigned)__cvta_generic_to_shared(pa);
                asm volatile("ldmatrix.sync.aligned.m8n8.x4.shared.b16 {%0,%1,%2,%3},[%4];"
                             : "=r"(a0), "=r"(a1), "=r"(a2), "=r"(a3) : "r"(addr));
            }
            #pragma unroll
            for (int nb = 0; nb < 4; ++nb) {
                int c = nb * 16;
                unsigned b0, b1, b2, b3;
                const __half* pb = &Ws[k16 + (lane & 15)][c + (lane >> 4) * 8];
                unsigned addr = (unsigned)__cvta_generic_to_shared(pb);
                asm volatile("ldmatrix.sync.aligned.m8n8.x4.trans.shared.b16 {%0,%1,%2,%3},[%4];"
                             : "=r"(b0), "=r"(b1), "=r"(b2), "=r"(b3) : "r"(addr));
                asm volatile("mma.sync.aligned.m16n8k16.row.col.f32.f16.f16.f32 "
                             "{%0,%1,%2,%3},{%4,%5,%6,%7},{%8,%9},{%0,%1,%2,%3};"
                             : "+f"(acc[2 * nb][0]), "+f"(acc[2 * nb][1]),
                               "+f"(acc[2 * nb][2]), "+f"(acc[2 * nb][3])
                             : "r"(a0), "r"(a1), "r"(a2), "r"(a3), "r"(b0), "r"(b1));
                asm volatile("mma.sync.aligned.m16n8k16.row.col.f32.f16.f16.f32 "
                             "{%0,%1,%2,%3},{%4,%5,%6,%7},{%8,%9},{%0,%1,%2,%3};"
                             : "+f"(acc[2 * nb + 1][0]), "+f"(acc[2 * nb + 1][1]),
                               "+f"(acc[2 * nb + 1][2]), "+f"(acc[2 * nb + 1][3])
                             : "r"(a0), "r"(a1), "r"(a2), "r"(a3), "r"(b2), "r"(b3));
            }
        }
        __syncthreads();
    }

    unsigned* outp = (unsigned*)g_hwh4;
    int gr0 = row0 + warp * 16 + (lane >> 2);
    #pragma unroll
    for (int nb = 0; nb < 8; ++nb) {
        __half2 lo = __floats2half2_rn(acc[nb][0], acc[nb][1]);
        __half2 hi = __floats2half2_rn(acc[nb][2], acc[nb][3]);
        int ci = nb * 4 + (lane & 3);
        if (gr0 < nrows)     outp[(size_t)gr0 * 32 + ci]       = *(unsigned*)&lo;
        if (gr0 + 8 < nrows) outp[(size_t)(gr0 + 8) * 32 + ci] = *(unsigned*)&hi;
    }
}

// ---------------- fused CSR aggregation + bias + relu + BN stats (R7 layout) ----------------
__device__ __forceinline__ void h8acc(uint4 raw, float c, float4& lo, float4& hi) {
    __half2 a = *(__half2*)&raw.x;
    __half2 b = *(__half2*)&raw.y;
    __half2 d = *(__half2*)&raw.z;
    __half2 e = *(__half2*)&raw.w;
    float2 f0 = __half22float2(a), f1 = __half22float2(b);
    float2 f2 = __half22float2(d), f3 = __half22float2(e);
    lo.x += c * f0.x; lo.y += c * f0.y; lo.z += c * f1.x; lo.w += c * f1.y;
    hi.x += c * f2.x; hi.y += c * f2.y; hi.z += c * f3.x; hi.w += c * f3.y;
}
__device__ __forceinline__ void h8scale(uint4 raw, float c, float4& lo, float4& hi) {
    __half2 a = *(__half2*)&raw.x;
    __half2 b = *(__half2*)&raw.y;
    __half2 d = *(__half2*)&raw.z;
    __half2 e = *(__half2*)&raw.w;
    float2 f0 = __half22float2(a), f1 = __half22float2(b);
    float2 f2 = __half22float2(d), f3 = __half22float2(e);
    lo = make_float4(c * f0.x, c * f0.y, c * f1.x, c * f1.y);
    hi = make_float4(c * f2.x, c * f2.y, c * f3.x, c * f3.y);
}

__global__ void __launch_bounds__(256) csr_agg_k(const float* __restrict__ bias,
                                                 float* __restrict__ stats) {
    __shared__ float ss[64], qq[64];
    int t = threadIdx.x;
    if (t < 64) { ss[t] = 0.f; qq[t] = 0.f; }
    __syncthreads();

    int idx = blockIdx.x * 256 + t;            // exactly NN*8
    int node = idx >> 3, q = idx & 7;
    int rs = g_rowptr[node], re = g_rowptr[node + 1];
    float d = g_dinv[node];
    float dd = d * d;
    float4 lo, hi;
    h8scale(g_hwh4[idx], dd, lo, hi);

    int j = rs;
    for (; j + 4 <= re; j += 4) {              // 4-way MLP
        float2 e0 = g_edge[j], e1 = g_edge[j + 1], e2 = g_edge[j + 2], e3 = g_edge[j + 3];
        uint4 v0 = g_hwh4[__float_as_int(e0.y) * 8 + q];
        uint4 v1 = g_hwh4[__float_as_int(e1.y) * 8 + q];
        uint4 v2 = g_hwh4[__float_as_int(e2.y) * 8 + q];
        uint4 v3 = g_hwh4[__float_as_int(e3.y) * 8 + q];
        h8acc(v0, e0.x, lo, hi);
        h8acc(v1, e1.x, lo, hi);
        h8acc(v2, e2.x, lo, hi);
        h8acc(v3, e3.x, lo, hi);
    }
    for (; j < re; ++j) {
        float2 e = g_edge[j];
        h8acc(g_hwh4[__float_as_int(e.y) * 8 + q], e.x, lo, hi);
    }

    float4 blo = ((const float4*)bias)[2 * q];
    float4 bhi = ((const float4*)bias)[2 * q + 1];
    lo.x = fmaxf(lo.x + blo.x, 0.f); lo.y = fmaxf(lo.y + blo.y, 0.f);
    lo.z = fmaxf(lo.z + blo.z, 0.f); lo.w = fmaxf(lo.w + blo.w, 0.f);
    hi.x = fmaxf(hi.x + bhi.x, 0.f); hi.y = fmaxf(hi.y + bhi.y, 0.f);
    hi.z = fmaxf(hi.z + bhi.z, 0.f); hi.w = fmaxf(hi.w + bhi.w, 0.f);
    g_agg4[node * 16 + 2 * q]     = lo;
    g_agg4[node * 16 + 2 * q + 1] = hi;

    float s[8] = {lo.x, lo.y, lo.z, lo.w, hi.x, hi.y, hi.z, hi.w};
    float sq[8];
    #pragma unroll
    for (int k = 0; k < 8; ++k) sq[k] = s[k] * s[k];
    #pragma unroll
    for (int k = 0; k < 8; ++k) {
        s[k]  += __shfl_down_sync(0xffffffffu, s[k], 16);
        sq[k] += __shfl_down_sync(0xffffffffu, sq[k], 16);
        s[k]  += __shfl_down_sync(0xffffffffu, s[k], 8);
        sq[k] += __shfl_down_sync(0xffffffffu, sq[k], 8);
    }
    if ((t & 31) < 8) {
        #pragma unroll
        for (int k = 0; k < 8; ++k) {
            atomicAdd(&ss[8 * q + k], s[k]);
            atomicAdd(&qq[8 * q + k], sq[k]);
        }
    }
    __syncthreads();
    if (t < 64) {
        atomicAdd(&stats[t], ss[t]);
        atomicAdd(&stats[64 + t], qq[t]);
    }
}

// ---------------- output layer: fused BN+residual, 64 -> 2, thread-per-row ----------------
__global__ void __launch_bounds__(256) gemm_out_k(const float* __restrict__ Z,
                                                  const float* __restrict__ W,
                                                  const float* __restrict__ gamma,
                                                  const float* __restrict__ beta,
                                                  const float* __restrict__ st) {
    __shared__ float w0[64], w1[64], ssc[64], ssh[64];
    if (threadIdx.x < 64) {
        int c = threadIdx.x;
        w0[c] = W[c * 2];
        w1[c] = W[c * 2 + 1];
        float s = st[c], q = st[64 + c];
        float m = s * (1.f / NN);
        float v = q * (1.f / NN) - m * m;
        float istd = rsqrtf(v + EPSV);
        float sc = istd * gamma[c];
        ssc[c] = sc;
        ssh[c] = beta[c] - m * sc;
    }
    __syncthreads();
    int row = blockIdx.x * 256 + threadIdx.x;
    if (row >= NN) return;
    const float4* zr = (const float4*)(Z + (size_t)row * 64);
    const float4* hr = (const float4*)((const float*)g_h4 + (size_t)row * 64);
    float a0 = 0.f, a1 = 0.f;
    #pragma unroll
    for (int k4 = 0; k4 < 16; ++k4) {
        float4 z = zr[k4];
        float4 o = hr[k4];
        int c = k4 * 4;
        float h0 = z.x * ssc[c + 0] + ssh[c + 0] + o.x;
        float h1 = z.y * ssc[c + 1] + ssh[c + 1] + o.y;
        float h2 = z.z * ssc[c + 2] + ssh[c + 2] + o.z;
        float h3 = z.w * ssc[c + 3] + ssh[c + 3] + o.w;
        a0 += h0 * w0[c + 0] + h1 * w0[c + 1] + h2 * w0[c + 2] + h3 * w0[c + 3];
        a1 += h0 * w1[c + 0] + h1 * w1[c + 1] + h2 * w1[c + 2] + h3 * w1[c + 3];
    }
    g_hw2[row] = make_float2(a0, a1);
}

// fused: CSR aggregation (2 channels) + segment pooling
__global__ void __launch_bounds__(256) csr2_pool_k(const int* __restrict__ bat) {
    __shared__ float sp[NB * OUTD];
    int t = threadIdx.x;
    if (t < NB * OUTD) sp[t] = 0.f;
    __syncthreads();
    int i = blockIdx.x * 256 + t;
    if (i < NN) {
        float d = g_dinv[i];
        float dd = d * d;
        float2 a = g_hw2[i];
        a.x *= dd; a.y *= dd;
        int rs = g_rowptr[i], re = g_rowptr[i + 1];
        int j = rs;
        for (; j + 4 <= re; j += 4) {
            float2 e0 = g_edge[j], e1 = g_edge[j + 1], e2 = g_edge[j + 2], e3 = g_edge[j + 3];
            float2 v0 = g_hw2[__float_as_int(e0.y)];
            float2 v1 = g_hw2[__float_as_int(e1.y)];
            float2 v2 = g_hw2[__float_as_int(e2.y)];
            float2 v3 = g_hw2[__float_as_int(e3.y)];
            a.x += e0.x * v0.x + e1.x * v1.x + e2.x * v2.x + e3.x * v3.x;
            a.y += e0.x * v0.y + e1.x * v1.y + e2.x * v2.y + e3.x * v3.y;
        }
        for (; j < re; ++j) {
            float2 e = g_edge[j];
            float2 v = g_hw2[__float_as_int(e.y)];
            a.x += e.x * v.x; a.y += e.x * v.y;
        }
        int b = bat[i];
        atomicAdd(&sp[2 * b],     a.x);
        atomicAdd(&sp[2 * b + 1], a.y);
    }
    __syncthreads();
    if (t < NB * OUTD) atomicAdd(&g_pool[t], sp[t]);
}

__global__ void final_k(const float* __restrict__ b_out, float* __restrict__ out) {
    int t = threadIdx.x;
    if (t < NB * OUTD) {
        int b = t >> 1, c = t & 1;
        out[t] = g_pool[t] / fmaxf(g_cnt[b], 1.f) + b_out[c];
    }
}

// ---------------- driver ----------------
extern "C" void kernel_launch(void* const* d_in, const int* in_sizes, int n_in,
                              void* d_out, int out_size) {
    const float* x       = (const float*)d_in[0];
    const float* W_in    = (const float*)d_in[1];
    const float* b_in    = (const float*)d_in[2];
    const float* W_h     = (const float*)d_in[3];
    const float* b_h     = (const float*)d_in[4];
    const float* W_out   = (const float*)d_in[5];
    const float* b_out   = (const float*)d_in[6];
    const float* bn_g    = (const float*)d_in[7];
    const float* bn_b    = (const float*)d_in[8];
    const int*   ei      = (const int*)d_in[9];
    const int*   bat     = (const int*)d_in[10];

    float* out = (float*)d_out;

    void *p_z, *p_st;
    cudaGetSymbolAddress(&p_z, g_agg4);
    cudaGetSymbolAddress(&p_st, g_stats);
    float* z  = (float*)p_z;
    float* st = (float*)p_st;   // 3 layers x 128

    // Fork: layer-1 GEMM depends only on inputs -> run concurrently with prep.
    cudaStream_t sB = 0;
    cudaEvent_t evFork = 0, evJoin = 0;
    bool forked =
        (cudaStreamCreateWithFlags(&sB, cudaStreamNonBlocking) == cudaSuccess) &&
        (cudaEventCreateWithFlags(&evFork, cudaEventDisableTiming) == cudaSuccess) &&
        (cudaEventCreateWithFlags(&evJoin, cudaEventDisableTiming) == cudaSuccess);

    if (forked) {
        cudaEventRecord(evFork, 0);
        cudaStreamWaitEvent(sB, evFork, 0);
        gemm_hmma<IND, 0><<<782, 256, 0, sB>>>(x, W_in, nullptr, nullptr, nullptr, NN);
        cudaEventRecord(evJoin, sB);
    }

    // prep chain (main stream)
    zero_k<<<391, 256>>>();
    count_k<<<4688, 256>>>(ei, bat);
    scan1_k<<<391, 256>>>();
    scan23_k<<<391, 256>>>();
    scatter_k<<<4688, 256>>>(ei);

    if (forked) {
        cudaStreamWaitEvent(0, evJoin, 0);     // join gemm1 before layer-1 aggregation
    } else {
        gemm_hmma<IND, 0><<<782, 256>>>(x, W_in, nullptr, nullptr, nullptr, NN);
    }

    // layer 1 aggregation
    csr_agg_k<<<3125, 256>>>(b_in, st);

    // layer 2
    gemm_hmma<HID, 1><<<782, 256>>>(z, W_h, bn_g, bn_b, st, NN);
    csr_agg_k<<<3125, 256>>>(b_h, st + 128);

    // layer 3
    gemm_hmma<HID, 2><<<782, 256>>>(z, W_h + HID * HID, bn_g + HID, bn_b + HID, st + 128, NN);
    csr_agg_k<<<3125, 256>>>(b_h + HID, st + 256);

    // output layer
    gemm_out_k<<<391, 256>>>(z, W_out, bn_g + 2 * HID, bn_b + 2 * HID, st + 256);
    csr2_pool_k<<<391, 256>>>(bat);
    final_k<<<1, 128>>>(b_out, out);

    if (forked) {
        cudaEventDestroy(evFork);
        cudaEventDestroy(evJoin);
        cudaStreamDestroy(sB);
    }
}